// round 16
// baseline (speedup 1.0000x reference)
#include <cuda_runtime.h>
#include <cstdint>

static constexpr int T_IN  = 1048576;
static constexpr int T_OUT = 1048564;              // T_IN - 12
static constexpr int ROWS  = 32;                   // 8 * 4
static constexpr int VEC_PER_ROW = T_OUT / 4;      // 262141 output float4s per row
static constexpr int F4_PER_ROW  = T_IN / 4;       // 262144 input float4s per row
static constexpr long TOTAL_F4   = (long)ROWS * F4_PER_ROW;   // 8388608
static constexpr int VEC_TILE = 512;               // output float4s per tile
static constexpr int NTILES = ROWS * 512;          // 16384 tiles
static constexpr int TILE_F4 = 515;                // input float4s per tile (12-float halo)
static constexpr int GRID2 = NTILES / 2;           // 8192 blocks, 2 tiles each

__device__ __forceinline__ uint32_t smem_u32(const void* p) {
    uint32_t a;
    asm("{ .reg .u64 x; cvta.to.shared.u64 x, %1; cvt.u32.u64 %0, x; }"
        : "=r"(a) : "l"(p));
    return a;
}

__device__ __forceinline__ void cp16_keep(uint32_t dst, const float4* src,
                                          int pred16, uint64_t pol) {
    asm volatile("cp.async.cg.shared.global.L2::cache_hint [%0], [%1], 16, %2, %3;"
                 :: "r"(dst), "l"(src), "r"(pred16), "l"(pol));
}

__global__ __launch_bounds__(256)
void conv13_dual2(const float4* __restrict__ x4, float* __restrict__ out,
                  const float* __restrict__ fd, const float* __restrict__ gauss) {
    __shared__ float4 sx[2][TILE_F4 + 1];
    __shared__ float sc[13];

    const int t = threadIdx.x;
    const uint32_t sb0 = smem_u32(&sx[0][0]);
    const uint32_t sb1 = smem_u32(&sx[1][0]);

    uint64_t pol;
    asm("createpolicy.fractional.L2::evict_last.b64 %0, 1.0;" : "=l"(pol));

    const int tid0 = blockIdx.x;
    const int tid1 = blockIdx.x + GRID2;

    const int row0 = tid0 >> 9, tile0 = tid0 & 511;
    const int row1 = tid1 >> 9, tile1 = tid1 & 511;
    const long gb0 = (long)row0 * F4_PER_ROW + (long)tile0 * VEC_TILE;
    const long gb1 = (long)row1 * F4_PER_ROW + (long)tile1 * VEC_TILE;

    // ---- Tile 0 prefetch (commit group 0) ----------------------------------
    #pragma unroll
    for (int r = 0; r < 2; ++r) {
        int i = t + r * 256;
        long g = gb0 + i;
        cp16_keep(sb0 + i * 16, x4 + g, (g < TOTAL_F4) ? 16 : 0, pol);
    }
    if (t < TILE_F4 - 512) {                       // i = 512..514
        int i = 512 + t;
        long g = gb0 + i;
        cp16_keep(sb0 + i * 16, x4 + g, (g < TOTAL_F4) ? 16 : 0, pol);
    }
    asm volatile("cp.async.commit_group;");

    // ---- Tile 1 prefetch (commit group 1) ----------------------------------
    #pragma unroll
    for (int r = 0; r < 2; ++r) {
        int i = t + r * 256;
        long g = gb1 + i;
        cp16_keep(sb1 + i * 16, x4 + g, (g < TOTAL_F4) ? 16 : 0, pol);
    }
    if (t < TILE_F4 - 512) {
        int i = 512 + t;
        long g = gb1 + i;
        cp16_keep(sb1 + i * 16, x4 + g, (g < TOTAL_F4) ? 16 : 0, pol);
    }
    asm volatile("cp.async.commit_group;");

    // ---- Compose composite 13-tap kernel while copies fly ------------------
    if (t < 13) {
        float acc = 0.0f;
        #pragma unroll
        for (int i = 0; i < 5; ++i) {
            int j = t - i;
            if (j >= 0 && j < 9) acc = fmaf(__ldg(fd + i), __ldg(gauss + j), acc);
        }
        sc[t] = acc;
    }

    // Each thread computes 2 ADJACENT output vec4s (v = 2t, 2t+1):
    // 5 smem float4 reads for 8 outputs (2.5x amplification vs 4x before).
    auto compute = [&](int row, int tile, const float4* __restrict__ buf) {
        const int vb = tile * VEC_TILE;
        const int v = 2 * t;                       // [0, 512) step 2
        const int gvec = vb + v;

        float4 q0 = buf[v],     q1 = buf[v + 1], q2 = buf[v + 2];
        float4 q3 = buf[v + 3], q4 = buf[v + 4];
        float xv[20] = {q0.x, q0.y, q0.z, q0.w,  q1.x, q1.y, q1.z, q1.w,
                        q2.x, q2.y, q2.z, q2.w,  q3.x, q3.y, q3.z, q3.w,
                        q4.x, q4.y, q4.z, q4.w};

        float y0 = 0.f, y1 = 0.f, y2 = 0.f, y3 = 0.f;
        float z0 = 0.f, z1 = 0.f, z2 = 0.f, z3 = 0.f;
        #pragma unroll
        for (int k = 0; k < 13; ++k) {
            float c = sc[k];
            y0 = fmaf(c, xv[k],     y0);
            y1 = fmaf(c, xv[k + 1], y1);
            y2 = fmaf(c, xv[k + 2], y2);
            y3 = fmaf(c, xv[k + 3], y3);
            z0 = fmaf(c, xv[k + 4], z0);
            z1 = fmaf(c, xv[k + 5], z1);
            z2 = fmaf(c, xv[k + 6], z2);
            z3 = fmaf(c, xv[k + 7], z3);
        }

        long o = (long)row * T_OUT + (long)gvec * 4;
        if (gvec < VEC_PER_ROW)
            __stcs(reinterpret_cast<float4*>(out + o), make_float4(y0, y1, y2, y3));
        if (gvec + 1 < VEC_PER_ROW)
            __stcs(reinterpret_cast<float4*>(out + o + 4), make_float4(z0, z1, z2, z3));
    };

    asm volatile("cp.async.wait_group 1;");        // tile0 resident, tile1 in flight
    __syncthreads();
    compute(row0, tile0, sx[0]);

    asm volatile("cp.async.wait_group 0;");        // tile1 resident
    __syncthreads();
    compute(row1, tile1, sx[1]);
}

extern "C" void kernel_launch(void* const* d_in, const int* in_sizes, int n_in,
                              void* d_out, int out_size) {
    const float4* x4   = (const float4*)d_in[0];
    const float* fd    = (const float*)d_in[1];
    const float* gauss = (const float*)d_in[2];
    float* out = (float*)d_out;

    conv13_dual2<<<GRID2, 256>>>(x4, out, fd, gauss);
}

// round 17
// speedup vs baseline: 1.0993x; 1.0993x over previous
#include <cuda_runtime.h>
#include <cstdint>

static constexpr int T_IN  = 1048576;
static constexpr int T_OUT = 1048564;              // T_IN - 12
static constexpr int ROWS  = 32;                   // 8 * 4
static constexpr int VEC_PER_ROW = T_OUT / 4;      // 262141 output float4s per row
static constexpr int F4_PER_ROW  = T_IN / 4;       // 262144 input float4s per row
static constexpr long TOTAL_F4   = (long)ROWS * F4_PER_ROW;   // 8388608
static constexpr int VEC_TILE = 512;               // output float4s per block-tile
static constexpr int NTILES = ROWS * 512;          // 16384 tiles
static constexpr int GRID2 = NTILES / 2;           // 8192 blocks, 2 tiles each
static constexpr int WVEC  = 64;                   // output vec4s per warp per tile
static constexpr int WF4   = 67;                   // input f4s per warp (64 + 3 halo)
static constexpr int WSTR  = 68;                   // padded smem stride (f4)

__device__ __forceinline__ uint32_t smem_u32(const void* p) {
    uint32_t a;
    asm("{ .reg .u64 x; cvta.to.shared.u64 x, %1; cvt.u32.u64 %0, x; }"
        : "=r"(a) : "l"(p));
    return a;
}

__device__ __forceinline__ void cp16_keep(uint32_t dst, const float4* src,
                                          int pred16, uint64_t pol) {
    asm volatile("cp.async.cg.shared.global.L2::cache_hint [%0], [%1], 16, %2, %3;"
                 :: "r"(dst), "l"(src), "r"(pred16), "l"(pol));
}

__global__ __launch_bounds__(256)
void conv13_warp(const float4* __restrict__ x4, float* __restrict__ out,
                 const float* __restrict__ fd, const float* __restrict__ gauss) {
    // [tile_stage][warp][f4]  — each warp touches ONLY its own regions.
    __shared__ float4 sx[2][8][WSTR];
    __shared__ float sc[13];

    const int t    = threadIdx.x;
    const int w    = t >> 5;
    const int lane = t & 31;

    uint64_t pol;
    asm("createpolicy.fractional.L2::evict_last.b64 %0, 1.0;" : "=l"(pol));

    const int tid0 = blockIdx.x;
    const int tid1 = blockIdx.x + GRID2;
    const int row0 = tid0 >> 9, tile0 = tid0 & 511;
    const int row1 = tid1 >> 9, tile1 = tid1 & 511;
    // Per-warp global f4 base: block tile base + warp sub-tile offset.
    const long gw0 = (long)row0 * F4_PER_ROW + (long)tile0 * VEC_TILE + w * WVEC;
    const long gw1 = (long)row1 * F4_PER_ROW + (long)tile1 * VEC_TILE + w * WVEC;

    const uint32_t sw0 = smem_u32(&sx[0][w][0]);
    const uint32_t sw1 = smem_u32(&sx[1][w][0]);

    // ---- Warp-local prefetch, tile 0 (commit group 0) ----------------------
    {
        long g = gw0 + lane;
        cp16_keep(sw0 + lane * 16, x4 + g, (g < TOTAL_F4) ? 16 : 0, pol);
        long g2 = gw0 + lane + 32;
        cp16_keep(sw0 + (lane + 32) * 16, x4 + g2, (g2 < TOTAL_F4) ? 16 : 0, pol);
        if (lane < WF4 - 64) {                     // halo f4s 64..66
            long g3 = gw0 + lane + 64;
            cp16_keep(sw0 + (lane + 64) * 16, x4 + g3, (g3 < TOTAL_F4) ? 16 : 0, pol);
        }
    }
    asm volatile("cp.async.commit_group;");

    // ---- Warp-local prefetch, tile 1 (commit group 1) ----------------------
    {
        long g = gw1 + lane;
        cp16_keep(sw1 + lane * 16, x4 + g, (g < TOTAL_F4) ? 16 : 0, pol);
        long g2 = gw1 + lane + 32;
        cp16_keep(sw1 + (lane + 32) * 16, x4 + g2, (g2 < TOTAL_F4) ? 16 : 0, pol);
        if (lane < WF4 - 64) {
            long g3 = gw1 + lane + 64;
            cp16_keep(sw1 + (lane + 64) * 16, x4 + g3, (g3 < TOTAL_F4) ? 16 : 0, pol);
        }
    }
    asm volatile("cp.async.commit_group;");

    // ---- Compose composite kernel (every warp writes the same values —
    //      benign race; __syncwarp below orders it within each warp) ---------
    if (lane < 13) {
        float acc = 0.0f;
        #pragma unroll
        for (int i = 0; i < 5; ++i) {
            int j = lane - i;
            if (j >= 0 && j < 9) acc = fmaf(__ldg(fd + i), __ldg(gauss + j), acc);
        }
        sc[lane] = acc;
    }

    // Per-warp compute: outputs v_local = lane, lane+32 of this warp's 64.
    auto compute = [&](int row, int tile, const float4* __restrict__ buf) {
        const int vb = tile * VEC_TILE + w * WVEC;
        #pragma unroll
        for (int r = 0; r < 2; ++r) {
            int v = lane + r * 32;                 // [0, 64)
            int gvec = vb + v;

            float4 q0 = buf[v], q1 = buf[v + 1], q2 = buf[v + 2], q3 = buf[v + 3];
            float xv[16] = {q0.x, q0.y, q0.z, q0.w,  q1.x, q1.y, q1.z, q1.w,
                            q2.x, q2.y, q2.z, q2.w,  q3.x, q3.y, q3.z, q3.w};

            float y0 = 0.f, y1 = 0.f, y2 = 0.f, y3 = 0.f;
            #pragma unroll
            for (int k = 0; k < 13; ++k) {
                float c = sc[k];
                y0 = fmaf(c, xv[k],     y0);
                y1 = fmaf(c, xv[k + 1], y1);
                y2 = fmaf(c, xv[k + 2], y2);
                y3 = fmaf(c, xv[k + 3], y3);
            }

            if (gvec < VEC_PER_ROW) {
                long o = (long)row * T_OUT + (long)gvec * 4;
                __stcs(reinterpret_cast<float4*>(out + o),
                       make_float4(y0, y1, y2, y3));
            }
        }
    };

    // No block barriers: each warp proceeds as soon as ITS data lands.
    asm volatile("cp.async.wait_group 1;");        // this warp's tile0 resident
    __syncwarp();
    compute(row0, tile0, &sx[0][w][0]);

    asm volatile("cp.async.wait_group 0;");        // this warp's tile1 resident
    __syncwarp();
    compute(row1, tile1, &sx[1][w][0]);
}

extern "C" void kernel_launch(void* const* d_in, const int* in_sizes, int n_in,
                              void* d_out, int out_size) {
    const float4* x4   = (const float4*)d_in[0];
    const float* fd    = (const float*)d_in[1];
    const float* gauss = (const float*)d_in[2];
    float* out = (float*)d_out;

    conv13_warp<<<GRID2, 256>>>(x4, out, fd, gauss);
}